// round 2
// baseline (speedup 1.0000x reference)
#include <cuda_runtime.h>

#define BT_TOK 32768      // B*T = 16*2048
#define IN_DIM 768
#define ENC 512
#define CDIM 128
#define NCB 8
#define CBS 1024
#define LOSS_BLOCKS 4096  // BT_TOK / 8 tokens-per-block

// ---------------- scratch (static device globals; no allocations) ----------
__device__ float g_R[BT_TOK * ENC];                    // residual (64MB)
__device__ float g_Ze[BT_TOK * CDIM];                  // z_e      (16MB)
__device__ unsigned long long g_packed[BT_TOK];        // (distkey<<32)|idx
__device__ float g_cbnorm[NCB * CBS];                  // ||c||^2
__device__ float g_lossPartial[NCB * LOSS_BLOCKS];     // deterministic partials

// ---------------- async-copy helpers ---------------------------------------
__device__ __forceinline__ void cp16(void* smem, const void* gmem) {
    unsigned s = (unsigned)__cvta_generic_to_shared(smem);
    asm volatile("cp.async.cg.shared.global [%0], [%1], 16;\n" :: "r"(s), "l"(gmem));
}
#define CP_COMMIT asm volatile("cp.async.commit_group;\n" ::)
#define CP_WAIT0  asm volatile("cp.async.wait_group 0;\n" ::)

// ---------------- SGEMM: 128x128 tile, BK=16, double-buffered, 256 thr -----
// C[M x N] = A[M x K] @ B[K x N]   (+bias | -=acc | A gathered via packed idx)
// Accumulation order per output element is k-ascending (bit-identical to R1).
template<bool BIAS, bool GATHER, bool SUB>
__global__ __launch_bounds__(256, 2) void sgemm2(
    const float* __restrict__ A, const float* __restrict__ B,
    float* __restrict__ C, const float* __restrict__ bias,
    const unsigned long long* __restrict__ packed,
    const float* __restrict__ gtab, int K, int N)
{
    __shared__ float As[2][16][128];
    __shared__ float Bs[2][16][128];
    const int tid = threadIdx.x;
    const int tx = tid & 15, ty = tid >> 4;
    const int m0 = blockIdx.x * 128;
    const int n0 = blockIdx.y * 128;

    const int ar = tid & 127;          // A row within tile
    const int ah = (tid >> 7) * 8;     // A k sub-offset: 0 or 8
    const int br = tid >> 4;           // B k-row 0..15
    const int bc = (tid & 15) * 4;     // B col chunk; second chunk at +64

    const float* aptr;
    if (GATHER) {
        unsigned idx = (unsigned)(packed[m0 + ar] & 0xffffffffu);
        aptr = gtab + (size_t)idx * CDIM;
    } else {
        aptr = A + (size_t)(m0 + ar) * K;
    }
    const float* bptr = B + n0;

    const int T = K >> 4;

    // ---- prologue: tile 0 ----
    float4 av0 = *(const float4*)(aptr + ah);
    float4 av1 = *(const float4*)(aptr + ah + 4);
    cp16(&Bs[0][br][bc],      bptr + (size_t)br * N + bc);
    cp16(&Bs[0][br][bc + 64], bptr + (size_t)br * N + bc + 64);
    As[0][ah + 0][ar] = av0.x; As[0][ah + 1][ar] = av0.y;
    As[0][ah + 2][ar] = av0.z; As[0][ah + 3][ar] = av0.w;
    As[0][ah + 4][ar] = av1.x; As[0][ah + 5][ar] = av1.y;
    As[0][ah + 6][ar] = av1.z; As[0][ah + 7][ar] = av1.w;
    CP_COMMIT;
    CP_WAIT0;
    __syncthreads();

    float acc[8][8];
#pragma unroll
    for (int i = 0; i < 8; ++i)
#pragma unroll
        for (int j = 0; j < 8; ++j) acc[i][j] = 0.f;

    for (int t = 0; t < T; ++t) {
        const int buf = t & 1;
        const bool pf = (t + 1 < T);
        const int kn = (t + 1) << 4;
        if (pf) {
            av0 = *(const float4*)(aptr + kn + ah);
            av1 = *(const float4*)(aptr + kn + ah + 4);
            cp16(&Bs[buf ^ 1][br][bc],      bptr + (size_t)(kn + br) * N + bc);
            cp16(&Bs[buf ^ 1][br][bc + 64], bptr + (size_t)(kn + br) * N + bc + 64);
            CP_COMMIT;
        }
#pragma unroll
        for (int k = 0; k < 16; ++k) {
            float a[8], b[8];
            *(float4*)(a)     = *(const float4*)&As[buf][k][ty * 8];
            *(float4*)(a + 4) = *(const float4*)&As[buf][k][ty * 8 + 4];
            *(float4*)(b)     = *(const float4*)&Bs[buf][k][tx * 8];
            *(float4*)(b + 4) = *(const float4*)&Bs[buf][k][tx * 8 + 4];
#pragma unroll
            for (int i = 0; i < 8; ++i)
#pragma unroll
                for (int j = 0; j < 8; ++j)
                    acc[i][j] += a[i] * b[j];
        }
        if (pf) {
            As[buf ^ 1][ah + 0][ar] = av0.x; As[buf ^ 1][ah + 1][ar] = av0.y;
            As[buf ^ 1][ah + 2][ar] = av0.z; As[buf ^ 1][ah + 3][ar] = av0.w;
            As[buf ^ 1][ah + 4][ar] = av1.x; As[buf ^ 1][ah + 5][ar] = av1.y;
            As[buf ^ 1][ah + 6][ar] = av1.z; As[buf ^ 1][ah + 7][ar] = av1.w;
            CP_WAIT0;
            __syncthreads();
        }
    }

#pragma unroll
    for (int i = 0; i < 8; ++i) {
        int m = m0 + ty * 8 + i;
        float* crow = C + (size_t)m * N + n0 + tx * 8;
        if (SUB) {
#pragma unroll
            for (int j = 0; j < 8; ++j) crow[j] -= acc[i][j];
        } else if (BIAS) {
#pragma unroll
            for (int j = 0; j < 8; ++j) crow[j] = acc[i][j] + bias[n0 + tx * 8 + j];
        } else {
#pragma unroll
            for (int j = 0; j < 8; ++j) crow[j] = acc[i][j];
        }
    }
}

// ---------------- distance + argmin kernel (double-buffered) ---------------
// acc = Ze[m] . cb[n]; d' = ||cb[n]||^2 - 2*acc  (||ze||^2 dropped: argmin-equiv)
// key = monotonic-float(d')<<32 | n ; atomicMin -> exact first-min tie behavior
__global__ __launch_bounds__(256, 2) void dist2_kernel(
    const float* __restrict__ Ze, const float* __restrict__ cb,
    const float* __restrict__ cbn, unsigned long long* __restrict__ packed)
{
    __shared__ float As[2][16][128];
    __shared__ float Bs[2][16][128];
    const int tid = threadIdx.x;
    const int tx = tid & 15, ty = tid >> 4;
    const int m0 = blockIdx.x * 128;
    const int n0 = blockIdx.y * 128;

    const int ar = tid & 127;
    const int ah = (tid >> 7) * 8;

    const float* aptr = Ze + (size_t)(m0 + ar) * CDIM;
    const float* bptr = cb + (size_t)(n0 + ar) * CDIM;   // row-gathered (transposed)

    const int T = CDIM >> 4;   // 8

    float4 av0 = *(const float4*)(aptr + ah);
    float4 av1 = *(const float4*)(aptr + ah + 4);
    float4 bv0 = *(const float4*)(bptr + ah);
    float4 bv1 = *(const float4*)(bptr + ah + 4);
    As[0][ah + 0][ar] = av0.x; As[0][ah + 1][ar] = av0.y;
    As[0][ah + 2][ar] = av0.z; As[0][ah + 3][ar] = av0.w;
    As[0][ah + 4][ar] = av1.x; As[0][ah + 5][ar] = av1.y;
    As[0][ah + 6][ar] = av1.z; As[0][ah + 7][ar] = av1.w;
    Bs[0][ah + 0][ar] = bv0.x; Bs[0][ah + 1][ar] = bv0.y;
    Bs[0][ah + 2][ar] = bv0.z; Bs[0][ah + 3][ar] = bv0.w;
    Bs[0][ah + 4][ar] = bv1.x; Bs[0][ah + 5][ar] = bv1.y;
    Bs[0][ah + 6][ar] = bv1.z; Bs[0][ah + 7][ar] = bv1.w;
    __syncthreads();

    float acc[8][8];
#pragma unroll
    for (int i = 0; i < 8; ++i)
#pragma unroll
        for (int j = 0; j < 8; ++j) acc[i][j] = 0.f;

    for (int t = 0; t < T; ++t) {
        const int buf = t & 1;
        const bool pf = (t + 1 < T);
        const int kn = (t + 1) << 4;
        if (pf) {
            av0 = *(const float4*)(aptr + kn + ah);
            av1 = *(const float4*)(aptr + kn + ah + 4);
            bv0 = *(const float4*)(bptr + kn + ah);
            bv1 = *(const float4*)(bptr + kn + ah + 4);
        }
#pragma unroll
        for (int k = 0; k < 16; ++k) {
            float a[8], b[8];
            *(float4*)(a)     = *(const float4*)&As[buf][k][ty * 8];
            *(float4*)(a + 4) = *(const float4*)&As[buf][k][ty * 8 + 4];
            *(float4*)(b)     = *(const float4*)&Bs[buf][k][tx * 8];
            *(float4*)(b + 4) = *(const float4*)&Bs[buf][k][tx * 8 + 4];
#pragma unroll
            for (int i = 0; i < 8; ++i)
#pragma unroll
                for (int j = 0; j < 8; ++j)
                    acc[i][j] += a[i] * b[j];
        }
        if (pf) {
            As[buf ^ 1][ah + 0][ar] = av0.x; As[buf ^ 1][ah + 1][ar] = av0.y;
            As[buf ^ 1][ah + 2][ar] = av0.z; As[buf ^ 1][ah + 3][ar] = av0.w;
            As[buf ^ 1][ah + 4][ar] = av1.x; As[buf ^ 1][ah + 5][ar] = av1.y;
            As[buf ^ 1][ah + 6][ar] = av1.z; As[buf ^ 1][ah + 7][ar] = av1.w;
            Bs[buf ^ 1][ah + 0][ar] = bv0.x; Bs[buf ^ 1][ah + 1][ar] = bv0.y;
            Bs[buf ^ 1][ah + 2][ar] = bv0.z; Bs[buf ^ 1][ah + 3][ar] = bv0.w;
            Bs[buf ^ 1][ah + 4][ar] = bv1.x; Bs[buf ^ 1][ah + 5][ar] = bv1.y;
            Bs[buf ^ 1][ah + 6][ar] = bv1.z; Bs[buf ^ 1][ah + 7][ar] = bv1.w;
            __syncthreads();
        }
    }

#pragma unroll
    for (int i = 0; i < 8; ++i) {
        unsigned long long best = ~0ull;
#pragma unroll
        for (int j = 0; j < 8; ++j) {
            int n = n0 + tx * 8 + j;
            float d = cbn[n] - 2.0f * acc[i][j];
            unsigned ib = __float_as_uint(d);
            ib ^= (ib & 0x80000000u) ? 0xffffffffu : 0x80000000u; // monotonic map
            unsigned long long key = ((unsigned long long)ib << 32) | (unsigned)n;
            if (key < best) best = key;
        }
#pragma unroll
        for (int off = 8; off >= 1; off >>= 1) {
            unsigned long long o = __shfl_xor_sync(0xffffffffu, best, off);
            if (o < best) best = o;
        }
        if (tx == 0) atomicMin(&packed[m0 + ty * 8 + i], best);
    }
}

// ---------------- helpers ---------------------------------------------------
__global__ void init_packed_kernel()
{
    int i = blockIdx.x * blockDim.x + threadIdx.x;
    if (i < BT_TOK) g_packed[i] = ~0ull;
}

// one warp per row: deterministic fixed-order reduction of ||row||^2
__global__ void norm_kernel(const float* __restrict__ cb, float* __restrict__ out, int rows)
{
    int w = (blockIdx.x * blockDim.x + threadIdx.x) >> 5;
    int lane = threadIdx.x & 31;
    if (w >= rows) return;
    const float* r = cb + (size_t)w * CDIM;
    float s = 0.f;
#pragma unroll
    for (int q = 0; q < 4; ++q) { float v = r[lane + q * 32]; s += v * v; }
#pragma unroll
    for (int off = 16; off >= 1; off >>= 1) s += __shfl_xor_sync(0xffffffffu, s, off);
    if (lane == 0) out[w] = s;
}

// per-token: write code (as float) + accumulate (z_e - z_q)^2, deterministic
__global__ __launch_bounds__(256) void loss_kernel(
    const float* __restrict__ Ze, const float* __restrict__ cb,
    const unsigned long long* __restrict__ packed,
    float* __restrict__ out_codes, int stage, float* __restrict__ partial)
{
    __shared__ float ws[8];
    int wid = threadIdx.x >> 5, lane = threadIdx.x & 31;
    int t = blockIdx.x * 8 + wid;
    unsigned idx = (unsigned)(packed[t] & 0xffffffffu);
    const float* ze = Ze + (size_t)t * CDIM;
    const float* zq = cb + (size_t)idx * CDIM;
    float s = 0.f;
#pragma unroll
    for (int q = 0; q < 4; ++q) {
        float d = ze[lane + q * 32] - zq[lane + q * 32];
        s += d * d;
    }
#pragma unroll
    for (int off = 16; off >= 1; off >>= 1) s += __shfl_xor_sync(0xffffffffu, s, off);
    if (lane == 0) {
        ws[wid] = s;
        out_codes[(size_t)t * NCB + stage] = (float)idx;
    }
    __syncthreads();
    if (threadIdx.x == 0) {
        float tot = 0.f;
        for (int w = 0; w < 8; ++w) tot += ws[w];
        partial[blockIdx.x] = tot;
    }
}

// fixed-tree final reduction -> out[BT_TOK*NCB] = total vq loss
__global__ void final_loss_kernel(const float* __restrict__ partial, float* __restrict__ out)
{
    __shared__ float s[256];
    float v = 0.f;
    const int per = (NCB * LOSS_BLOCKS) / 256;   // 128
    for (int q = 0; q < per; ++q) v += partial[threadIdx.x * per + q];
    s[threadIdx.x] = v;
    __syncthreads();
    for (int st = 128; st > 0; st >>= 1) {
        if (threadIdx.x < st) s[threadIdx.x] += s[threadIdx.x + st];
        __syncthreads();
    }
    if (threadIdx.x == 0)
        out[(size_t)BT_TOK * NCB] = 1.25f * s[0] / (float)((size_t)BT_TOK * CDIM);
}

// ---------------- launch ----------------------------------------------------
extern "C" void kernel_launch(void* const* d_in, const int* in_sizes, int n_in,
                              void* d_out, int out_size)
{
    const float* z    = (const float*)d_in[0];   // (16,2048,768)
    const float* Win  = (const float*)d_in[1];   // (768,512)
    const float* bin  = (const float*)d_in[2];   // (512,)
    const float* cbs  = (const float*)d_in[3];   // (8,1024,128)
    const float* inw  = (const float*)d_in[4];   // (8,512,128)
    const float* outw = (const float*)d_in[5];   // (8,128,512)
    float* out = (float*)d_out;

    float *gR, *gZe, *gCbn, *gLP;
    unsigned long long* gPk;
    cudaGetSymbolAddress((void**)&gR,  g_R);
    cudaGetSymbolAddress((void**)&gZe, g_Ze);
    cudaGetSymbolAddress((void**)&gCbn, g_cbnorm);
    cudaGetSymbolAddress((void**)&gLP, g_lossPartial);
    cudaGetSymbolAddress((void**)&gPk, g_packed);

    // 1. residual = z @ W_in + b_in
    sgemm2<true, false, false><<<dim3(BT_TOK / 128, ENC / 128), 256>>>(
        z, Win, gR, bin, nullptr, nullptr, IN_DIM, ENC);

    // 2. codebook norms (all stages at once)
    norm_kernel<<<(NCB * CBS * 32) / 256, 256>>>(cbs, gCbn, NCB * CBS);

    for (int i = 0; i < NCB; ++i) {
        const float* cb_i = cbs + (size_t)i * CBS * CDIM;

        init_packed_kernel<<<BT_TOK / 256, 256>>>();

        // z_e = R @ in_w[i]
        sgemm2<false, false, false><<<dim3(BT_TOK / 128, CDIM / 128), 256>>>(
            gR, inw + (size_t)i * ENC * CDIM, gZe, nullptr, nullptr, nullptr, ENC, CDIM);

        // distances + argmin
        dist2_kernel<<<dim3(BT_TOK / 128, CBS / 128), 256>>>(
            gZe, cb_i, gCbn + i * CBS, gPk);

        // codes + loss partials
        loss_kernel<<<LOSS_BLOCKS, 256>>>(gZe, cb_i, gPk, out, i, gLP + i * LOSS_BLOCKS);

        // R -= cb[idx] @ out_w[i]   (gathered A)
        sgemm2<false, true, true><<<dim3(BT_TOK / 128, ENC / 128), 256>>>(
            nullptr, outw + (size_t)i * CDIM * ENC, gR, nullptr, gPk, cb_i, CDIM, ENC);
    }

    final_loss_kernel<<<1, 256>>>(gLP, out);
}

// round 3
// speedup vs baseline: 1.0036x; 1.0036x over previous
#include <cuda_runtime.h>

#define BT_TOK 32768      // B*T = 16*2048
#define IN_DIM 768
#define ENC 512
#define CDIM 128
#define NCB 8
#define CBS 1024
#define LOSS_BLOCKS 4096  // BT_TOK / 8 tokens-per-block

// ---------------- scratch (static device globals; no allocations) ----------
__device__ float g_R[BT_TOK * ENC];                    // residual (64MB)
__device__ float g_Ze[BT_TOK * CDIM];                  // z_e      (16MB)
__device__ unsigned long long g_packed[BT_TOK];        // (distkey<<32)|idx
__device__ float g_cbnorm[NCB * CBS];                  // ||c||^2
__device__ float g_lossPartial[NCB * LOSS_BLOCKS];     // deterministic partials

// ---------------- async-copy helpers ---------------------------------------
__device__ __forceinline__ void cp16(void* smem, const void* gmem) {
    unsigned s = (unsigned)__cvta_generic_to_shared(smem);
    asm volatile("cp.async.cg.shared.global [%0], [%1], 16;\n" :: "r"(s), "l"(gmem));
}
#define CP_COMMIT asm volatile("cp.async.commit_group;\n" ::)
#define CP_WAIT0  asm volatile("cp.async.wait_group 0;\n" ::)

// ---------------- SGEMM: 128x128 tile, BK=16, smem + register double-buffer
// C[M x N] = A[M x K] @ B[K x N]   (+bias | -=acc | A gathered via packed idx)
// Per-output-element accumulation: single fp32 acc, k strictly ascending
// (bit-identical to rounds 1/2).
template<bool BIAS, bool GATHER, bool SUB, bool INITPK>
__global__ __launch_bounds__(256, 2) void sgemm3(
    const float* __restrict__ A, const float* __restrict__ B,
    float* __restrict__ C, const float* __restrict__ bias,
    const unsigned long long* __restrict__ packed,
    const float* __restrict__ gtab,
    unsigned long long* __restrict__ pk_init, int K, int N)
{
    __shared__ float As[2][16][128];
    __shared__ float Bs[2][16][128];
    const int tid = threadIdx.x;
    const int tx = tid & 15, ty = tid >> 4;
    const int m0 = blockIdx.x * 128;
    const int n0 = blockIdx.y * 128;

    if (INITPK && tid < 128) pk_init[m0 + tid] = ~0ull;

    const int ar = tid & 127;          // A row within tile
    const int ah = (tid >> 7) * 8;     // A k sub-offset: 0 or 8
    const int br = tid >> 4;           // B k-row 0..15
    const int bc = (tid & 15) * 4;     // B col chunk; second chunk at +64

    const float* aptr;
    if (GATHER) {
        unsigned idx = (unsigned)(packed[m0 + ar] & 0xffffffffu);
        aptr = gtab + (size_t)idx * CDIM;
    } else {
        aptr = A + (size_t)(m0 + ar) * K;
    }
    const float* bptr = B + n0;

    const int T = K >> 4;

    // ---- prologue: tile 0 ----
    float4 av0 = *(const float4*)(aptr + ah);
    float4 av1 = *(const float4*)(aptr + ah + 4);
    cp16(&Bs[0][br][bc],      bptr + (size_t)br * N + bc);
    cp16(&Bs[0][br][bc + 64], bptr + (size_t)br * N + bc + 64);
    As[0][ah + 0][ar] = av0.x; As[0][ah + 1][ar] = av0.y;
    As[0][ah + 2][ar] = av0.z; As[0][ah + 3][ar] = av0.w;
    As[0][ah + 4][ar] = av1.x; As[0][ah + 5][ar] = av1.y;
    As[0][ah + 6][ar] = av1.z; As[0][ah + 7][ar] = av1.w;
    CP_COMMIT;
    CP_WAIT0;
    __syncthreads();

    float acc[8][8];
#pragma unroll
    for (int i = 0; i < 8; ++i)
#pragma unroll
        for (int j = 0; j < 8; ++j) acc[i][j] = 0.f;

    float fa[2][8], fb[2][8];

    for (int t = 0; t < T; ++t) {
        const int buf = t & 1;
        const bool pf = (t + 1 < T);
        const int kn = (t + 1) << 4;
        if (pf) {
            av0 = *(const float4*)(aptr + kn + ah);
            av1 = *(const float4*)(aptr + kn + ah + 4);
            cp16(&Bs[buf ^ 1][br][bc],      bptr + (size_t)(kn + br) * N + bc);
            cp16(&Bs[buf ^ 1][br][bc + 64], bptr + (size_t)(kn + br) * N + bc + 64);
            CP_COMMIT;
        }
        // register fragment double-buffer over the 16 k-steps
        *(float4*)(fa[0])     = *(const float4*)&As[buf][0][ty * 8];
        *(float4*)(fa[0] + 4) = *(const float4*)&As[buf][0][ty * 8 + 4];
        *(float4*)(fb[0])     = *(const float4*)&Bs[buf][0][tx * 8];
        *(float4*)(fb[0] + 4) = *(const float4*)&Bs[buf][0][tx * 8 + 4];
#pragma unroll
        for (int k = 0; k < 16; ++k) {
            const int c = k & 1;
            if (k < 15) {
                *(float4*)(fa[c ^ 1])     = *(const float4*)&As[buf][k + 1][ty * 8];
                *(float4*)(fa[c ^ 1] + 4) = *(const float4*)&As[buf][k + 1][ty * 8 + 4];
                *(float4*)(fb[c ^ 1])     = *(const float4*)&Bs[buf][k + 1][tx * 8];
                *(float4*)(fb[c ^ 1] + 4) = *(const float4*)&Bs[buf][k + 1][tx * 8 + 4];
            }
#pragma unroll
            for (int i = 0; i < 8; ++i)
#pragma unroll
                for (int j = 0; j < 8; ++j)
                    acc[i][j] += fa[c][i] * fb[c][j];
        }
        if (pf) {
            As[buf ^ 1][ah + 0][ar] = av0.x; As[buf ^ 1][ah + 1][ar] = av0.y;
            As[buf ^ 1][ah + 2][ar] = av0.z; As[buf ^ 1][ah + 3][ar] = av0.w;
            As[buf ^ 1][ah + 4][ar] = av1.x; As[buf ^ 1][ah + 5][ar] = av1.y;
            As[buf ^ 1][ah + 6][ar] = av1.z; As[buf ^ 1][ah + 7][ar] = av1.w;
            CP_WAIT0;
            __syncthreads();
        }
    }

#pragma unroll
    for (int i = 0; i < 8; ++i) {
        int m = m0 + ty * 8 + i;
        float* crow = C + (size_t)m * N + n0 + tx * 8;
        if (SUB) {
#pragma unroll
            for (int j = 0; j < 8; ++j) crow[j] -= acc[i][j];
        } else if (BIAS) {
#pragma unroll
            for (int j = 0; j < 8; ++j) crow[j] = acc[i][j] + bias[n0 + tx * 8 + j];
        } else {
#pragma unroll
            for (int j = 0; j < 8; ++j) crow[j] = acc[i][j];
        }
    }
}

// ---------------- distance + argmin kernel (smem + register DB) ------------
// acc = Ze[m] . cb[n]; d' = ||cb[n]||^2 - 2*acc  (||ze||^2 dropped: argmin-equiv)
// key = monotonic-float(d')<<32 | n ; atomicMin -> exact first-min tie behavior
__global__ __launch_bounds__(256, 2) void dist3_kernel(
    const float* __restrict__ Ze, const float* __restrict__ cb,
    const float* __restrict__ cbn, unsigned long long* __restrict__ packed)
{
    __shared__ float As[2][16][128];
    __shared__ float Bs[2][16][128];
    const int tid = threadIdx.x;
    const int tx = tid & 15, ty = tid >> 4;
    const int m0 = blockIdx.x * 128;
    const int n0 = blockIdx.y * 128;

    const int ar = tid & 127;
    const int ah = (tid >> 7) * 8;

    const float* aptr = Ze + (size_t)(m0 + ar) * CDIM;
    const float* bptr = cb + (size_t)(n0 + ar) * CDIM;   // row-gathered (transposed)

    const int T = CDIM >> 4;   // 8

    float4 av0 = *(const float4*)(aptr + ah);
    float4 av1 = *(const float4*)(aptr + ah + 4);
    float4 bv0 = *(const float4*)(bptr + ah);
    float4 bv1 = *(const float4*)(bptr + ah + 4);
    As[0][ah + 0][ar] = av0.x; As[0][ah + 1][ar] = av0.y;
    As[0][ah + 2][ar] = av0.z; As[0][ah + 3][ar] = av0.w;
    As[0][ah + 4][ar] = av1.x; As[0][ah + 5][ar] = av1.y;
    As[0][ah + 6][ar] = av1.z; As[0][ah + 7][ar] = av1.w;
    Bs[0][ah + 0][ar] = bv0.x; Bs[0][ah + 1][ar] = bv0.y;
    Bs[0][ah + 2][ar] = bv0.z; Bs[0][ah + 3][ar] = bv0.w;
    Bs[0][ah + 4][ar] = bv1.x; Bs[0][ah + 5][ar] = bv1.y;
    Bs[0][ah + 6][ar] = bv1.z; Bs[0][ah + 7][ar] = bv1.w;
    __syncthreads();

    float acc[8][8];
#pragma unroll
    for (int i = 0; i < 8; ++i)
#pragma unroll
        for (int j = 0; j < 8; ++j) acc[i][j] = 0.f;

    float fa[2][8], fb[2][8];

    for (int t = 0; t < T; ++t) {
        const int buf = t & 1;
        const bool pf = (t + 1 < T);
        const int kn = (t + 1) << 4;
        if (pf) {
            av0 = *(const float4*)(aptr + kn + ah);
            av1 = *(const float4*)(aptr + kn + ah + 4);
            bv0 = *(const float4*)(bptr + kn + ah);
            bv1 = *(const float4*)(bptr + kn + ah + 4);
        }
        *(float4*)(fa[0])     = *(const float4*)&As[buf][0][ty * 8];
        *(float4*)(fa[0] + 4) = *(const float4*)&As[buf][0][ty * 8 + 4];
        *(float4*)(fb[0])     = *(const float4*)&Bs[buf][0][tx * 8];
        *(float4*)(fb[0] + 4) = *(const float4*)&Bs[buf][0][tx * 8 + 4];
#pragma unroll
        for (int k = 0; k < 16; ++k) {
            const int c = k & 1;
            if (k < 15) {
                *(float4*)(fa[c ^ 1])     = *(const float4*)&As[buf][k + 1][ty * 8];
                *(float4*)(fa[c ^ 1] + 4) = *(const float4*)&As[buf][k + 1][ty * 8 + 4];
                *(float4*)(fb[c ^ 1])     = *(const float4*)&Bs[buf][k + 1][tx * 8];
                *(float4*)(fb[c ^ 1] + 4) = *(const float4*)&Bs[buf][k + 1][tx * 8 + 4];
            }
#pragma unroll
            for (int i = 0; i < 8; ++i)
#pragma unroll
                for (int j = 0; j < 8; ++j)
                    acc[i][j] += fa[c][i] * fb[c][j];
        }
        if (pf) {
            As[buf ^ 1][ah + 0][ar] = av0.x; As[buf ^ 1][ah + 1][ar] = av0.y;
            As[buf ^ 1][ah + 2][ar] = av0.z; As[buf ^ 1][ah + 3][ar] = av0.w;
            As[buf ^ 1][ah + 4][ar] = av1.x; As[buf ^ 1][ah + 5][ar] = av1.y;
            As[buf ^ 1][ah + 6][ar] = av1.z; As[buf ^ 1][ah + 7][ar] = av1.w;
            Bs[buf ^ 1][ah + 0][ar] = bv0.x; Bs[buf ^ 1][ah + 1][ar] = bv0.y;
            Bs[buf ^ 1][ah + 2][ar] = bv0.z; Bs[buf ^ 1][ah + 3][ar] = bv0.w;
            Bs[buf ^ 1][ah + 4][ar] = bv1.x; Bs[buf ^ 1][ah + 5][ar] = bv1.y;
            Bs[buf ^ 1][ah + 6][ar] = bv1.z; Bs[buf ^ 1][ah + 7][ar] = bv1.w;
            __syncthreads();
        }
    }

#pragma unroll
    for (int i = 0; i < 8; ++i) {
        unsigned long long best = ~0ull;
#pragma unroll
        for (int j = 0; j < 8; ++j) {
            int n = n0 + tx * 8 + j;
            float d = cbn[n] - 2.0f * acc[i][j];
            unsigned ib = __float_as_uint(d);
            ib ^= (ib & 0x80000000u) ? 0xffffffffu : 0x80000000u; // monotonic map
            unsigned long long key = ((unsigned long long)ib << 32) | (unsigned)n;
            if (key < best) best = key;
        }
#pragma unroll
        for (int off = 8; off >= 1; off >>= 1) {
            unsigned long long o = __shfl_xor_sync(0xffffffffu, best, off);
            if (o < best) best = o;
        }
        if (tx == 0) atomicMin(&packed[m0 + ty * 8 + i], best);
    }
}

// ---------------- helpers ---------------------------------------------------
// one warp per row: deterministic fixed-order reduction of ||row||^2
__global__ void norm_kernel(const float* __restrict__ cb, float* __restrict__ out, int rows)
{
    int w = (blockIdx.x * blockDim.x + threadIdx.x) >> 5;
    int lane = threadIdx.x & 31;
    if (w >= rows) return;
    const float* r = cb + (size_t)w * CDIM;
    float s = 0.f;
#pragma unroll
    for (int q = 0; q < 4; ++q) { float v = r[lane + q * 32]; s += v * v; }
#pragma unroll
    for (int off = 16; off >= 1; off >>= 1) s += __shfl_xor_sync(0xffffffffu, s, off);
    if (lane == 0) out[w] = s;
}

// per-token: write code (as float) + accumulate (z_e - z_q)^2, deterministic
__global__ __launch_bounds__(256) void loss_kernel(
    const float* __restrict__ Ze, const float* __restrict__ cb,
    const unsigned long long* __restrict__ packed,
    float* __restrict__ out_codes, int stage, float* __restrict__ partial)
{
    __shared__ float ws[8];
    int wid = threadIdx.x >> 5, lane = threadIdx.x & 31;
    int t = blockIdx.x * 8 + wid;
    unsigned idx = (unsigned)(packed[t] & 0xffffffffu);
    const float* ze = Ze + (size_t)t * CDIM;
    const float* zq = cb + (size_t)idx * CDIM;
    float s = 0.f;
#pragma unroll
    for (int q = 0; q < 4; ++q) {
        float d = ze[lane + q * 32] - zq[lane + q * 32];
        s += d * d;
    }
#pragma unroll
    for (int off = 16; off >= 1; off >>= 1) s += __shfl_xor_sync(0xffffffffu, s, off);
    if (lane == 0) {
        ws[wid] = s;
        out_codes[(size_t)t * NCB + stage] = (float)idx;
    }
    __syncthreads();
    if (threadIdx.x == 0) {
        float tot = 0.f;
        for (int w = 0; w < 8; ++w) tot += ws[w];
        partial[blockIdx.x] = tot;
    }
}

// fixed-tree final reduction -> out[BT_TOK*NCB] = total vq loss
__global__ void final_loss_kernel(const float* __restrict__ partial, float* __restrict__ out)
{
    __shared__ float s[256];
    float v = 0.f;
    const int per = (NCB * LOSS_BLOCKS) / 256;   // 128
    for (int q = 0; q < per; ++q) v += partial[threadIdx.x * per + q];
    s[threadIdx.x] = v;
    __syncthreads();
    for (int st = 128; st > 0; st >>= 1) {
        if (threadIdx.x < st) s[threadIdx.x] += s[threadIdx.x + st];
        __syncthreads();
    }
    if (threadIdx.x == 0)
        out[(size_t)BT_TOK * NCB] = 1.25f * s[0] / (float)((size_t)BT_TOK * CDIM);
}

// ---------------- launch ----------------------------------------------------
extern "C" void kernel_launch(void* const* d_in, const int* in_sizes, int n_in,
                              void* d_out, int out_size)
{
    const float* z    = (const float*)d_in[0];   // (16,2048,768)
    const float* Win  = (const float*)d_in[1];   // (768,512)
    const float* bin  = (const float*)d_in[2];   // (512,)
    const float* cbs  = (const float*)d_in[3];   // (8,1024,128)
    const float* inw  = (const float*)d_in[4];   // (8,512,128)
    const float* outw = (const float*)d_in[5];   // (8,128,512)
    float* out = (float*)d_out;

    float *gR, *gZe, *gCbn, *gLP;
    unsigned long long* gPk;
    cudaGetSymbolAddress((void**)&gR,  g_R);
    cudaGetSymbolAddress((void**)&gZe, g_Ze);
    cudaGetSymbolAddress((void**)&gCbn, g_cbnorm);
    cudaGetSymbolAddress((void**)&gLP, g_lossPartial);
    cudaGetSymbolAddress((void**)&gPk, g_packed);

    // 1. residual = z @ W_in + b_in
    sgemm3<true, false, false, false><<<dim3(BT_TOK / 128, ENC / 128), 256>>>(
        z, Win, gR, bin, nullptr, nullptr, nullptr, IN_DIM, ENC);

    // 2. codebook norms (all stages at once)
    norm_kernel<<<(NCB * CBS * 32) / 256, 256>>>(cbs, gCbn, NCB * CBS);

    for (int i = 0; i < NCB; ++i) {
        const float* cb_i = cbs + (size_t)i * CBS * CDIM;

        // z_e = R @ in_w[i]   (also re-inits packed[] for this stage)
        sgemm3<false, false, false, true><<<dim3(BT_TOK / 128, CDIM / 128), 256>>>(
            gR, inw + (size_t)i * ENC * CDIM, gZe, nullptr, nullptr, nullptr, gPk,
            ENC, CDIM);

        // distances + argmin
        dist3_kernel<<<dim3(BT_TOK / 128, CBS / 128), 256>>>(
            gZe, cb_i, gCbn + i * CBS, gPk);

        // codes + loss partials
        loss_kernel<<<LOSS_BLOCKS, 256>>>(gZe, cb_i, gPk, out, i, gLP + i * LOSS_BLOCKS);

        // R -= cb[idx] @ out_w[i]   (gathered A)
        sgemm3<false, true, true, false><<<dim3(BT_TOK / 128, ENC / 128), 256>>>(
            nullptr, outw + (size_t)i * CDIM * ENC, gR, nullptr, gPk, cb_i, nullptr,
            CDIM, ENC);
    }

    final_loss_kernel<<<1, 256>>>(gLP, out);
}

// round 4
// speedup vs baseline: 1.2389x; 1.2344x over previous
#include <cuda_runtime.h>

#define BT_TOK 32768      // B*T = 16*2048
#define IN_DIM 768
#define ENC 512
#define CDIM 128
#define NCB 8
#define CBS 1024

// ---------------- scratch (static device globals; no allocations) ----------
__device__ float g_R[BT_TOK * ENC];                    // residual (64MB)
__device__ float g_Ze[BT_TOK * CDIM];                  // z_e      (16MB)
__device__ unsigned long long g_packed[BT_TOK];        // (distkey<<32)|idx
__device__ float g_cbnorm[NCB * CBS];                  // ||c||^2
__device__ float g_G[NCB * CBS * ENC];                 // cb @ out_w tables (16MB)
__device__ float g_lossPartial[NCB * BT_TOK];          // deterministic partials

// ---------------- async-copy + f32x2 helpers --------------------------------
__device__ __forceinline__ void cp16(void* smem, const void* gmem) {
    unsigned s = (unsigned)__cvta_generic_to_shared(smem);
    asm volatile("cp.async.cg.shared.global [%0], [%1], 16;\n" :: "r"(s), "l"(gmem));
}
#define CP_COMMIT asm volatile("cp.async.commit_group;\n" ::)
#define CP_WAIT0  asm volatile("cp.async.wait_group 0;\n" ::)

__device__ __forceinline__ unsigned long long pack2(float lo, float hi) {
    unsigned long long r;
    asm("mov.b64 %0, {%1, %2};" : "=l"(r) : "f"(lo), "f"(hi));
    return r;
}
__device__ __forceinline__ void unpack2(float& lo, float& hi, unsigned long long v) {
    asm("mov.b64 {%0, %1}, %2;" : "=f"(lo), "=f"(hi) : "l"(v));
}
// d = a*b + d  on two packed fp32 lanes; each lane is an exact IEEE FFMA(rn),
// so per-element accumulation chains stay bit-identical to scalar FFMA.
__device__ __forceinline__ void fma2(unsigned long long& d, unsigned long long a,
                                     unsigned long long b) {
    asm("fma.rn.f32x2 %0, %1, %2, %0;" : "+l"(d) : "l"(a), "l"(b));
}

// ---------------- SGEMM: 128x128 tile, BK=16, smem DB, FFMA2 core ----------
// C[M x N] = A[M x K] @ B[K x N]   (+bias | A gathered via packed idx)
// Per-output-element: single fp32 acc, k strictly ascending (bit-identical
// to rounds 1-3). blockIdx.z batches independent problems via strides.
template<bool BIAS, bool GATHER, bool INITPK>
__global__ __launch_bounds__(256, 2) void sgemm4(
    const float* __restrict__ A, const float* __restrict__ B,
    float* __restrict__ C, const float* __restrict__ bias,
    const unsigned long long* __restrict__ packed,
    const float* __restrict__ gtab,
    unsigned long long* __restrict__ pk_init, int K, int N,
    size_t strA, size_t strB, size_t strC)
{
    __shared__ float As[2][16][128];
    __shared__ float Bs[2][16][128];
    A += (size_t)blockIdx.z * strA;
    B += (size_t)blockIdx.z * strB;
    C += (size_t)blockIdx.z * strC;
    const int tid = threadIdx.x;
    const int tx = tid & 15, ty = tid >> 4;
    const int m0 = blockIdx.x * 128;
    const int n0 = blockIdx.y * 128;

    if (INITPK && blockIdx.y == 0 && tid < 128) pk_init[m0 + tid] = ~0ull;

    const int ar = tid & 127;          // A row within tile
    const int ah = (tid >> 7) * 8;     // A k sub-offset: 0 or 8
    const int br = tid >> 4;           // B k-row 0..15
    const int bc = (tid & 15) * 4;     // B col chunk; second chunk at +64

    const float* aptr;
    if (GATHER) {
        unsigned idx = (unsigned)(packed[m0 + ar] & 0xffffffffu);
        aptr = gtab + (size_t)idx * CDIM;
    } else {
        aptr = A + (size_t)(m0 + ar) * K;
    }
    const float* bptr = B + n0;

    const int T = K >> 4;

    // ---- prologue: tile 0 ----
    float4 av0 = *(const float4*)(aptr + ah);
    float4 av1 = *(const float4*)(aptr + ah + 4);
    cp16(&Bs[0][br][bc],      bptr + (size_t)br * N + bc);
    cp16(&Bs[0][br][bc + 64], bptr + (size_t)br * N + bc + 64);
    As[0][ah + 0][ar] = av0.x; As[0][ah + 1][ar] = av0.y;
    As[0][ah + 2][ar] = av0.z; As[0][ah + 3][ar] = av0.w;
    As[0][ah + 4][ar] = av1.x; As[0][ah + 5][ar] = av1.y;
    As[0][ah + 6][ar] = av1.z; As[0][ah + 7][ar] = av1.w;
    CP_COMMIT;
    CP_WAIT0;
    __syncthreads();

    unsigned long long acc2[8][4];
#pragma unroll
    for (int i = 0; i < 8; ++i)
#pragma unroll
        for (int j = 0; j < 4; ++j) acc2[i][j] = 0ull;

    for (int t = 0; t < T; ++t) {
        const int buf = t & 1;
        const bool pf = (t + 1 < T);
        const int kn = (t + 1) << 4;
        if (pf) {
            av0 = *(const float4*)(aptr + kn + ah);
            av1 = *(const float4*)(aptr + kn + ah + 4);
            cp16(&Bs[buf ^ 1][br][bc],      bptr + (size_t)(kn + br) * N + bc);
            cp16(&Bs[buf ^ 1][br][bc + 64], bptr + (size_t)(kn + br) * N + bc + 64);
            CP_COMMIT;
        }
#pragma unroll
        for (int k = 0; k < 16; ++k) {
            float a[8];
            *(float4*)(a)     = *(const float4*)&As[buf][k][ty * 8];
            *(float4*)(a + 4) = *(const float4*)&As[buf][k][ty * 8 + 4];
            float4 b0 = *(const float4*)&Bs[buf][k][tx * 8];
            float4 b1 = *(const float4*)&Bs[buf][k][tx * 8 + 4];
            unsigned long long bb[4];
            bb[0] = pack2(b0.x, b0.y); bb[1] = pack2(b0.z, b0.w);
            bb[2] = pack2(b1.x, b1.y); bb[3] = pack2(b1.z, b1.w);
#pragma unroll
            for (int i = 0; i < 8; ++i) {
                unsigned long long ai = pack2(a[i], a[i]);
#pragma unroll
                for (int j = 0; j < 4; ++j) fma2(acc2[i][j], ai, bb[j]);
            }
        }
        if (pf) {
            As[buf ^ 1][ah + 0][ar] = av0.x; As[buf ^ 1][ah + 1][ar] = av0.y;
            As[buf ^ 1][ah + 2][ar] = av0.z; As[buf ^ 1][ah + 3][ar] = av0.w;
            As[buf ^ 1][ah + 4][ar] = av1.x; As[buf ^ 1][ah + 5][ar] = av1.y;
            As[buf ^ 1][ah + 6][ar] = av1.z; As[buf ^ 1][ah + 7][ar] = av1.w;
            CP_WAIT0;
            __syncthreads();
        }
    }

#pragma unroll
    for (int i = 0; i < 8; ++i) {
        float c[8];
#pragma unroll
        for (int j = 0; j < 4; ++j) unpack2(c[2 * j], c[2 * j + 1], acc2[i][j]);
        int m = m0 + ty * 8 + i;
        float* crow = C + (size_t)m * N + n0 + tx * 8;
        if (BIAS) {
#pragma unroll
            for (int j = 0; j < 8; ++j) crow[j] = c[j] + bias[n0 + tx * 8 + j];
        } else {
#pragma unroll
            for (int j = 0; j < 8; ++j) crow[j] = c[j];
        }
    }
}

// ---------------- distance + argmin kernel (FFMA2 core) --------------------
// acc = Ze[m] . cb[n]; d' = ||cb[n]||^2 - 2*acc  (||ze||^2 dropped: argmin-equiv)
// key = monotonic-float(d')<<32 | n ; atomicMin -> exact first-min tie behavior
__global__ __launch_bounds__(256, 2) void dist4_kernel(
    const float* __restrict__ Ze, const float* __restrict__ cb,
    const float* __restrict__ cbn, unsigned long long* __restrict__ packed)
{
    __shared__ float As[2][16][128];
    __shared__ float Bs[2][16][128];
    const int tid = threadIdx.x;
    const int tx = tid & 15, ty = tid >> 4;
    const int m0 = blockIdx.x * 128;
    const int n0 = blockIdx.y * 128;

    const int ar = tid & 127;
    const int ah = (tid >> 7) * 8;

    const float* aptr = Ze + (size_t)(m0 + ar) * CDIM;
    const float* bptr = cb + (size_t)(n0 + ar) * CDIM;   // row-gathered (transposed)

    const int T = CDIM >> 4;   // 8

    float4 av0 = *(const float4*)(aptr + ah);
    float4 av1 = *(const float4*)(aptr + ah + 4);
    float4 bv0 = *(const float4*)(bptr + ah);
    float4 bv1 = *(const float4*)(bptr + ah + 4);
    As[0][ah + 0][ar] = av0.x; As[0][ah + 1][ar] = av0.y;
    As[0][ah + 2][ar] = av0.z; As[0][ah + 3][ar] = av0.w;
    As[0][ah + 4][ar] = av1.x; As[0][ah + 5][ar] = av1.y;
    As[0][ah + 6][ar] = av1.z; As[0][ah + 7][ar] = av1.w;
    Bs[0][ah + 0][ar] = bv0.x; Bs[0][ah + 1][ar] = bv0.y;
    Bs[0][ah + 2][ar] = bv0.z; Bs[0][ah + 3][ar] = bv0.w;
    Bs[0][ah + 4][ar] = bv1.x; Bs[0][ah + 5][ar] = bv1.y;
    Bs[0][ah + 6][ar] = bv1.z; Bs[0][ah + 7][ar] = bv1.w;
    __syncthreads();

    unsigned long long acc2[8][4];
#pragma unroll
    for (int i = 0; i < 8; ++i)
#pragma unroll
        for (int j = 0; j < 4; ++j) acc2[i][j] = 0ull;

    for (int t = 0; t < T; ++t) {
        const int buf = t & 1;
        const bool pf = (t + 1 < T);
        const int kn = (t + 1) << 4;
        if (pf) {
            av0 = *(const float4*)(aptr + kn + ah);
            av1 = *(const float4*)(aptr + kn + ah + 4);
            bv0 = *(const float4*)(bptr + kn + ah);
            bv1 = *(const float4*)(bptr + kn + ah + 4);
        }
#pragma unroll
        for (int k = 0; k < 16; ++k) {
            float a[8];
            *(float4*)(a)     = *(const float4*)&As[buf][k][ty * 8];
            *(float4*)(a + 4) = *(const float4*)&As[buf][k][ty * 8 + 4];
            float4 b0 = *(const float4*)&Bs[buf][k][tx * 8];
            float4 b1 = *(const float4*)&Bs[buf][k][tx * 8 + 4];
            unsigned long long bb[4];
            bb[0] = pack2(b0.x, b0.y); bb[1] = pack2(b0.z, b0.w);
            bb[2] = pack2(b1.x, b1.y); bb[3] = pack2(b1.z, b1.w);
#pragma unroll
            for (int i = 0; i < 8; ++i) {
                unsigned long long ai = pack2(a[i], a[i]);
#pragma unroll
                for (int j = 0; j < 4; ++j) fma2(acc2[i][j], ai, bb[j]);
            }
        }
        if (pf) {
            As[buf ^ 1][ah + 0][ar] = av0.x; As[buf ^ 1][ah + 1][ar] = av0.y;
            As[buf ^ 1][ah + 2][ar] = av0.z; As[buf ^ 1][ah + 3][ar] = av0.w;
            As[buf ^ 1][ah + 4][ar] = av1.x; As[buf ^ 1][ah + 5][ar] = av1.y;
            As[buf ^ 1][ah + 6][ar] = av1.z; As[buf ^ 1][ah + 7][ar] = av1.w;
            Bs[buf ^ 1][ah + 0][ar] = bv0.x; Bs[buf ^ 1][ah + 1][ar] = bv0.y;
            Bs[buf ^ 1][ah + 2][ar] = bv0.z; Bs[buf ^ 1][ah + 3][ar] = bv0.w;
            Bs[buf ^ 1][ah + 4][ar] = bv1.x; Bs[buf ^ 1][ah + 5][ar] = bv1.y;
            Bs[buf ^ 1][ah + 6][ar] = bv1.z; Bs[buf ^ 1][ah + 7][ar] = bv1.w;
            __syncthreads();
        }
    }

#pragma unroll
    for (int i = 0; i < 8; ++i) {
        float c[8];
#pragma unroll
        for (int j = 0; j < 4; ++j) unpack2(c[2 * j], c[2 * j + 1], acc2[i][j]);
        unsigned long long best = ~0ull;
#pragma unroll
        for (int j = 0; j < 8; ++j) {
            int n = n0 + tx * 8 + j;
            float d = cbn[n] - 2.0f * c[j];
            unsigned ib = __float_as_uint(d);
            ib ^= (ib & 0x80000000u) ? 0xffffffffu : 0x80000000u; // monotonic map
            unsigned long long key = ((unsigned long long)ib << 32) | (unsigned)n;
            if (key < best) best = key;
        }
#pragma unroll
        for (int off = 8; off >= 1; off >>= 1) {
            unsigned long long o = __shfl_xor_sync(0xffffffffu, best, off);
            if (o < best) best = o;
        }
        if (tx == 0) atomicMin(&packed[m0 + ty * 8 + i], best);
    }
}

// ---------------- helpers ---------------------------------------------------
// one warp per row: deterministic fixed-order reduction of ||row||^2
__global__ void norm_kernel(const float* __restrict__ cb, float* __restrict__ out, int rows)
{
    int w = (blockIdx.x * blockDim.x + threadIdx.x) >> 5;
    int lane = threadIdx.x & 31;
    if (w >= rows) return;
    const float* r = cb + (size_t)w * CDIM;
    float s = 0.f;
#pragma unroll
    for (int q = 0; q < 4; ++q) { float v = r[lane + q * 32]; s += v * v; }
#pragma unroll
    for (int off = 16; off >= 1; off >>= 1) s += __shfl_xor_sync(0xffffffffu, s, off);
    if (lane == 0) out[w] = s;
}

// per-token fused epilogue: write code, loss partial, and R -= G[idx]
// (R update arithmetic identical to previous dec-GEMM path: G rows hold the
//  same bit-exact dot products, and the single subtraction is unchanged.)
__global__ __launch_bounds__(128) void fused_update_kernel(
    const float* __restrict__ Ze, const float* __restrict__ cb,
    const float* __restrict__ G, const unsigned long long* __restrict__ packed,
    float* __restrict__ out_codes, int stage, float* __restrict__ partial,
    float* __restrict__ R)
{
    __shared__ float red[128];
    const int t = blockIdx.x;
    const int tid = threadIdx.x;
    const unsigned idx = (unsigned)(packed[t] & 0xffffffffu);

    // loss term for this token: sum over CDIM of (ze - zq)^2 (fixed-tree order)
    float d = Ze[(size_t)t * CDIM + tid] - cb[(size_t)idx * CDIM + tid];
    red[tid] = d * d;
    __syncthreads();
#pragma unroll
    for (int st = 64; st > 0; st >>= 1) {
        if (tid < st) red[tid] += red[tid + st];
        __syncthreads();
    }
    if (tid == 0) {
        partial[t] = red[0];
        out_codes[(size_t)t * NCB + stage] = (float)idx;
    }

    // R[t] -= G[idx]  (512 floats = 128 float4)
    float4* R4 = (float4*)(R + (size_t)t * ENC);
    const float4* G4 = (const float4*)(G + (size_t)idx * ENC);
    float4 r = R4[tid];
    float4 g = G4[tid];
    r.x -= g.x; r.y -= g.y; r.z -= g.z; r.w -= g.w;
    R4[tid] = r;
}

// fixed-tree final reduction -> out[BT_TOK*NCB] = total vq loss
__global__ void final_loss_kernel(const float* __restrict__ partial, float* __restrict__ out)
{
    __shared__ float s[256];
    float v = 0.f;
    const int per = (NCB * BT_TOK) / 256;   // 1024
    for (int q = 0; q < per; ++q) v += partial[threadIdx.x * per + q];
    s[threadIdx.x] = v;
    __syncthreads();
    for (int st = 128; st > 0; st >>= 1) {
        if (threadIdx.x < st) s[threadIdx.x] += s[threadIdx.x + st];
        __syncthreads();
    }
    if (threadIdx.x == 0)
        out[(size_t)BT_TOK * NCB] = 1.25f * s[0] / (float)((size_t)BT_TOK * CDIM);
}

// ---------------- launch ----------------------------------------------------
extern "C" void kernel_launch(void* const* d_in, const int* in_sizes, int n_in,
                              void* d_out, int out_size)
{
    const float* z    = (const float*)d_in[0];   // (16,2048,768)
    const float* Win  = (const float*)d_in[1];   // (768,512)
    const float* bin  = (const float*)d_in[2];   // (512,)
    const float* cbs  = (const float*)d_in[3];   // (8,1024,128)
    const float* inw  = (const float*)d_in[4];   // (8,512,128)
    const float* outw = (const float*)d_in[5];   // (8,128,512)
    float* out = (float*)d_out;

    float *gR, *gZe, *gCbn, *gLP, *gG;
    unsigned long long* gPk;
    cudaGetSymbolAddress((void**)&gR,  g_R);
    cudaGetSymbolAddress((void**)&gZe, g_Ze);
    cudaGetSymbolAddress((void**)&gCbn, g_cbnorm);
    cudaGetSymbolAddress((void**)&gLP, g_lossPartial);
    cudaGetSymbolAddress((void**)&gG,  g_G);
    cudaGetSymbolAddress((void**)&gPk, g_packed);

    // 1. residual = z @ W_in + b_in
    sgemm4<true, false, false><<<dim3(BT_TOK / 128, ENC / 128, 1), 256>>>(
        z, Win, gR, bin, nullptr, nullptr, nullptr, IN_DIM, ENC, 0, 0, 0);

    // 2. codebook norms (all stages at once)
    norm_kernel<<<(NCB * CBS * 32) / 256, 256>>>(cbs, gCbn, NCB * CBS);

    // 3. dec tables: G_i = cb_i @ out_w_i for all 8 stages (batched over z)
    sgemm4<false, false, false><<<dim3(CBS / 128, ENC / 128, NCB), 256>>>(
        cbs, outw, gG, nullptr, nullptr, nullptr, nullptr, CDIM, ENC,
        (size_t)CBS * CDIM, (size_t)CDIM * ENC, (size_t)CBS * ENC);

    for (int i = 0; i < NCB; ++i) {
        const float* cb_i = cbs + (size_t)i * CBS * CDIM;

        // z_e = R @ in_w[i]   (also re-inits packed[] for this stage)
        sgemm4<false, false, true><<<dim3(BT_TOK / 128, CDIM / 128, 1), 256>>>(
            gR, inw + (size_t)i * ENC * CDIM, gZe, nullptr, nullptr, nullptr, gPk,
            ENC, CDIM, 0, 0, 0);

        // distances + argmin
        dist4_kernel<<<dim3(BT_TOK / 128, CBS / 128), 256>>>(
            gZe, cb_i, gCbn + i * CBS, gPk);

        // codes + loss partials + R -= G[idx]
        fused_update_kernel<<<BT_TOK, 128>>>(
            gZe, cb_i, gG + (size_t)i * CBS * ENC, gPk, out, i,
            gLP + (size_t)i * BT_TOK, gR);
    }

    final_loss_kernel<<<1, 256>>>(gLP, out);
}